// round 7
// baseline (speedup 1.0000x reference)
#include <cuda_runtime.h>
#include <math.h>

// Problem constants (fixed by the dataset)
#define P_PRED 3
#define E_EV   128
#define S_MAX  64
#define CHUNKS 16
#define TPB    128

#define TIME_TOL 0.1f
#define DECAY    0.8f
#define RES_D    0.03

// Scratch (no device allocation allowed anywhere).
__device__ double g_partials[2048];       // [0..63] log-sums, [64..] integral partials
__device__ float  g_pref[S_MAX][P_PRED][E_EV + 4];
__device__ int    g_counter = 0;

__device__ __forceinline__ float final_intensity(float raw, float base) {
    return (raw >= 0.0f) ? fmaxf(raw, base) : __expf(raw);
}

__device__ __forceinline__ float lam_of(float w, float feat, float b) {
    float raw = __fadd_rn(b, __fmul_rn(w, feat));   // mirror ref: mul then add
    return final_intensity(raw, b);
}

// Branchless count of events with (t - st[e]) > 0.1f on sorted st[0..128).
// Bit-exact vs the reference's f32 predicate (monotone in te).
__device__ __forceinline__ int cut_count(const float* __restrict__ st, float t) {
    int c = 0;
#pragma unroll
    for (int step = 64; step >= 1; step >>= 1)
        if ((t - st[c + step - 1]) > TIME_TOL) c += step;
    if ((t - st[c]) > TIME_TOL) ++c;    // handles c == 128 exactly
    return c;
}

// ---------------- Kernel A: per-sample prefix scan + log-sum term ----------------
__global__ __launch_bounds__(TPB)
void hawkes_prep(const float* __restrict__ event_times,
                 const float* __restrict__ event_mask,
                 const float* __restrict__ base,
                 const float* __restrict__ weight) {
    const int s   = blockIdx.x;
    const int tid = threadIdx.x;

    __shared__ float st[P_PRED][E_EV];
    __shared__ float sm[P_PRED][E_EV];
    __shared__ float pref[P_PRED][E_EV + 1];
    __shared__ float sb[P_PRED], sw[P_PRED];
    __shared__ double red[TPB];

    const float* et = event_times + (size_t)s * P_PRED * E_EV;
    const float* em = event_mask  + (size_t)s * P_PRED * E_EV;
    for (int i = tid; i < P_PRED * E_EV; i += TPB) {
        int p = i >> 7, e = i & 127;
        st[p][e] = et[i];
        sm[p][e] = em[i];
    }
    if (tid < P_PRED) { sb[tid] = base[tid]; sw[tid] = weight[tid]; }
    __syncthreads();

    // f64 warp-scan of m_e * __expf(0.8*te) per predicate (warp w -> pred w).
    const int wid = tid >> 5, lane = tid & 31;
    if (wid < P_PRED) {
        double carry = 0.0;
#pragma unroll
        for (int seg = 0; seg < E_EV / 32; ++seg) {
            int e = seg * 32 + lane;
            double v = (double)__fmul_rn(sm[wid][e], __expf(__fmul_rn(DECAY, st[wid][e])));
#pragma unroll
            for (int o = 1; o < 32; o <<= 1) {
                double n = __shfl_up_sync(0xffffffffu, v, o);
                if (lane >= o) v += n;
            }
            v += carry;
            pref[wid][e + 1] = (float)v;
            carry = __shfl_sync(0xffffffffu, v, 31);
        }
        if (lane == 0) pref[wid][0] = 0.0f;
    }
    __syncthreads();

    // Publish pref for the integral kernel.
    for (int i = tid; i < P_PRED * (E_EV + 1); i += TPB) {
        int p = i / (E_EV + 1), e = i % (E_EV + 1);
        g_pref[s][p][e] = pref[p][e];
    }

    const float b0 = sb[0], b1 = sb[1], b2 = sb[2];
    const float w0 = sw[0], w1 = sw[1], w2 = sw[2];

    // ---- log-sum term: each head's own event times, eq >= 1, mask > 0 ----
    double acc = 0.0;
    for (int q = tid; q < P_PRED * E_EV; q += TPB) {
        int h = q >> 7, eq = q & 127;
        if (eq >= 1 && sm[h][eq] > 0.0f) {
            float tq = st[h][eq];
            float edk = __expf(__fmul_rn(-DECAY, tq));
            float feat;
            if (h == 0) {
                float k1 = __fmul_rn(edk, pref[1][cut_count(st[1], tq)]);
                float k2 = __fmul_rn(edk, pref[2][cut_count(st[2], tq)]);
                feat = __fadd_rn(k1, k2);
            } else {
                feat = __fmul_rn(edk, pref[0][cut_count(st[0], tq)]);
            }
            float bh = (h == 0) ? b0 : (h == 1) ? b1 : b2;
            float wh = (h == 0) ? w0 : (h == 1) ? w1 : w2;
            acc += (double)logf(lam_of(wh, feat, bh));
        }
    }

    red[tid] = acc;
    __syncthreads();
#pragma unroll
    for (int off = TPB / 2; off > 0; off >>= 1) {
        if (tid < off) red[tid] += red[tid + off];
        __syncthreads();
    }
    if (tid == 0) g_partials[s] = red[0];
}

// ---------------- Kernel B: integral term + final deterministic reduce ----------------
__global__ __launch_bounds__(TPB)
void hawkes_integral(const float* __restrict__ event_times,
                     const float* __restrict__ base,
                     const float* __restrict__ weight,
                     const void*  __restrict__ tmax_ptr,
                     float* __restrict__ out,
                     int S) {
    const int s     = blockIdx.x / CHUNKS;
    const int chunk = blockIdx.x % CHUNKS;
    const int tid   = threadIdx.x;
    const int NB    = gridDim.x;

    __shared__ float st[P_PRED][E_EV];
    __shared__ float pref[P_PRED][E_EV + 1];
    __shared__ float sb[P_PRED], sw[P_PRED];
    __shared__ double red[TPB];
    __shared__ int islast;

    const float* et = event_times + (size_t)s * P_PRED * E_EV;
    for (int i = tid; i < P_PRED * E_EV; i += TPB) {
        int p = i >> 7, e = i & 127;
        st[p][e] = et[i];
    }
    for (int i = tid; i < P_PRED * (E_EV + 1); i += TPB) {
        int p = i / (E_EV + 1), e = i % (E_EV + 1);
        pref[p][e] = g_pref[s][p][e];
    }
    if (tid < P_PRED) { sb[tid] = base[tid]; sw[tid] = weight[tid]; }
    __syncthreads();

    // Grid count G = ceil(T_max / 0.03); T_max may arrive as int or f32.
    int tmax_i = *(const int*)tmax_ptr;
    if (!(tmax_i > 0 && tmax_i < 1000000)) tmax_i = (int)(*(const float*)tmax_ptr);
    const int G = (int)ceil((double)tmax_i / RES_D);

    const float b0 = sb[0], b1 = sb[1], b2 = sb[2];
    const float w0 = sw[0], w1 = sw[1], w2 = sw[2];

    const int per = (G + CHUNKS - 1) / CHUNKS;
    const int gs = chunk * per;
    const int ge = min(gs + per, G);

    double acc_int = 0.0;
    for (int g = gs + tid; g < ge; g += TPB) {
        float t = (float)((double)g * RES_D);   // matches np.arange(f64) -> f32
        float edk = __expf(__fmul_rn(-DECAY, t));

        // Three interleaved branchless searches (independent LDS chains).
        int c0 = 0, c1 = 0, c2 = 0;
#pragma unroll
        for (int step = 64; step >= 1; step >>= 1) {
            if ((t - st[0][c0 + step - 1]) > TIME_TOL) c0 += step;
            if ((t - st[1][c1 + step - 1]) > TIME_TOL) c1 += step;
            if ((t - st[2][c2 + step - 1]) > TIME_TOL) c2 += step;
        }
        if ((t - st[0][c0]) > TIME_TOL) ++c0;
        if ((t - st[1][c1]) > TIME_TOL) ++c1;
        if ((t - st[2][c2]) > TIME_TOL) ++c2;

        float k0 = __fmul_rn(edk, pref[0][c0]);
        float k1 = __fmul_rn(edk, pref[1][c1]);
        float k2 = __fmul_rn(edk, pref[2][c2]);

        // BODY = [[0,1,1],[1,0,0],[1,0,0]]
        float l0 = lam_of(w0, __fadd_rn(k1, k2), b0);
        float l1 = lam_of(w1, k0, b1);
        float l2 = lam_of(w2, k0, b2);
        acc_int += (double)(l0 + l1 + l2);
    }

    red[tid] = -(double)RES_D * acc_int;
    __syncthreads();
#pragma unroll
    for (int off = TPB / 2; off > 0; off >>= 1) {
        if (tid < off) red[tid] += red[tid + off];
        __syncthreads();
    }
    if (tid == 0) {
        g_partials[S + blockIdx.x] = red[0];
        __threadfence();
        int old = atomicAdd(&g_counter, 1);
        islast = (old == NB - 1) ? 1 : 0;
    }
    __syncthreads();

    // Last block: fixed-order deterministic final reduce over S + NB partials.
    if (islast) {
        __threadfence();
        const int TOT = S + NB;
        const int PERT = (TOT + TPB - 1) / TPB;
        double a = 0.0;
        int b0i = tid * PERT;
        for (int i = 0; i < PERT; ++i) {
            int idx = b0i + i;
            if (idx < TOT) a += g_partials[idx];
        }
        red[tid] = a;
        __syncthreads();
#pragma unroll
        for (int off = TPB / 2; off > 0; off >>= 1) {
            if (tid < off) red[tid] += red[tid + off];
            __syncthreads();
        }
        if (tid == 0) {
            out[0] = (float)red[0];
            g_counter = 0;   // reset for next graph replay
        }
    }
}

extern "C" void kernel_launch(void* const* d_in, const int* in_sizes, int n_in,
                              void* d_out, int out_size) {
    const float* event_times = (const float*)d_in[0];
    const float* event_mask  = (const float*)d_in[1];
    const float* base        = (const float*)d_in[2];
    const float* weight      = (const float*)d_in[3];
    const void*  tmax        = d_in[4];

    int S = in_sizes[0] / (P_PRED * E_EV);

    hawkes_prep<<<S, TPB>>>(event_times, event_mask, base, weight);
    hawkes_integral<<<S * CHUNKS, TPB>>>(event_times, base, weight, tmax,
                                         (float*)d_out, S);
}

// round 8
// speedup vs baseline: 1.4351x; 1.4351x over previous
#include <cuda_runtime.h>
#include <math.h>
#include <float.h>

// Problem constants (fixed by the dataset)
#define P_PRED 3
#define E_EV   128
#define CHUNKS 2
#define TPB    256

#define TIME_TOL 0.1f
#define DECAY    0.8f
#define RES_D    0.03

// Scratch (no device allocation allowed anywhere).
__device__ double g_partials[2048];
__device__ int    g_counter = 0;

__device__ __forceinline__ float final_intensity(float raw, float base) {
    return (raw >= 0.0f) ? fmaxf(raw, base) : __expf(raw);
}

__device__ __forceinline__ float lam_of(float w, float feat, float b) {
    float raw = __fadd_rn(b, __fmul_rn(w, feat));   // mirror ref: mul then add
    return final_intensity(raw, b);
}

// Branchless count of events with (t - st[e]) > 0.1f on sorted st[0..128).
// Bit-exact vs the reference's f32 predicate (monotone in te).
__device__ __forceinline__ int cut_count(const float* __restrict__ st, float t) {
    int c = 0;
#pragma unroll
    for (int step = 64; step >= 1; step >>= 1)
        if ((t - st[c + step - 1]) > TIME_TOL) c += step;
    if ((t - st[c]) > TIME_TOL) ++c;    // handles c == 128 exactly
    return c;
}

__global__ __launch_bounds__(TPB)
void hawkes_fused(const float* __restrict__ event_times,
                  const float* __restrict__ event_mask,
                  const float* __restrict__ base,
                  const float* __restrict__ weight,
                  const void*  __restrict__ tmax_ptr,
                  float* __restrict__ out) {
    const int s     = blockIdx.x / CHUNKS;
    const int chunk = blockIdx.x % CHUNKS;
    const int tid   = threadIdx.x;
    const int NB    = gridDim.x;

    __shared__ float st[P_PRED][E_EV + 1];    // sorted times + FLT_MAX sentinel
    __shared__ float sm[P_PRED][E_EV];        // masks
    __shared__ float pref[P_PRED][E_EV + 1];  // f32 prefix of m*exp(0.8*te) (f64 scan)
    __shared__ float sb[P_PRED], sw[P_PRED];
    __shared__ double red[TPB];
    __shared__ int islast;

    const float* et = event_times + (size_t)s * P_PRED * E_EV;
    const float* em = event_mask  + (size_t)s * P_PRED * E_EV;
    for (int i = tid; i < P_PRED * E_EV; i += TPB) {
        int p = i >> 7, e = i & 127;
        st[p][e] = et[i];
        sm[p][e] = em[i];
    }
    if (tid < P_PRED) {
        sb[tid] = base[tid];
        sw[tid] = weight[tid];
        st[tid][E_EV] = FLT_MAX;              // advance-loop sentinel
    }
    __syncthreads();

    // f64 warp-scan of m_e * __expf(0.8*te) per predicate (warp w -> pred w).
    const int wid = tid >> 5, lane = tid & 31;
    if (wid < P_PRED) {
        double carry = 0.0;
#pragma unroll
        for (int seg = 0; seg < E_EV / 32; ++seg) {
            int e = seg * 32 + lane;
            double v = (double)__fmul_rn(sm[wid][e], __expf(__fmul_rn(DECAY, st[wid][e])));
#pragma unroll
            for (int o = 1; o < 32; o <<= 1) {
                double n = __shfl_up_sync(0xffffffffu, v, o);
                if (lane >= o) v += n;
            }
            v += carry;
            pref[wid][e + 1] = (float)v;
            carry = __shfl_sync(0xffffffffu, v, 31);
        }
        if (lane == 0) pref[wid][0] = 0.0f;
    }
    __syncthreads();

    // Grid count G = ceil(T_max / 0.03); T_max may arrive as int or f32.
    int tmax_i = *(const int*)tmax_ptr;
    if (!(tmax_i > 0 && tmax_i < 1000000)) tmax_i = (int)(*(const float*)tmax_ptr);
    const int G = (int)ceil((double)tmax_i / RES_D);

    const float b0 = sb[0], b1 = sb[1], b2 = sb[2];
    const float w0 = sw[0], w1 = sw[1], w2 = sw[2];

    double acc = 0.0;

    // ---- integral term: contiguous per-thread range + incremental advance ----
    const int per = (G + CHUNKS - 1) / CHUNKS;
    const int gs  = chunk * per;
    const int ge  = min(gs + per, G);
    const int npt = (per + TPB - 1) / TPB;
    const int r0  = gs + tid * npt;
    const int r1  = min(r0 + npt, ge);

    if (r0 < r1) {
        // One bit-exact binary search for the first point (3 interleaved chains).
        float t0 = (float)((double)r0 * RES_D);
        int c0 = 0, c1 = 0, c2 = 0;
#pragma unroll
        for (int step = 64; step >= 1; step >>= 1) {
            if ((t0 - st[0][c0 + step - 1]) > TIME_TOL) c0 += step;
            if ((t0 - st[1][c1 + step - 1]) > TIME_TOL) c1 += step;
            if ((t0 - st[2][c2 + step - 1]) > TIME_TOL) c2 += step;
        }
        if ((t0 - st[0][c0]) > TIME_TOL) ++c0;
        if ((t0 - st[1][c1]) > TIME_TOL) ++c1;
        if ((t0 - st[2][c2]) > TIME_TOL) ++c2;

        double acc_int = 0.0;
        for (int g = r0; g < r1; ++g) {
            float t = (float)((double)g * RES_D);   // matches np.arange(f64) -> f32
            // Monotone incremental advance with the identical predicate.
            while ((t - st[0][c0]) > TIME_TOL) ++c0;
            while ((t - st[1][c1]) > TIME_TOL) ++c1;
            while ((t - st[2][c2]) > TIME_TOL) ++c2;

            float edk = __expf(__fmul_rn(-DECAY, t));
            float k0 = __fmul_rn(edk, pref[0][c0]);
            float k1 = __fmul_rn(edk, pref[1][c1]);
            float k2 = __fmul_rn(edk, pref[2][c2]);

            // BODY = [[0,1,1],[1,0,0],[1,0,0]]
            float l0 = lam_of(w0, __fadd_rn(k1, k2), b0);
            float l1 = lam_of(w1, k0, b1);
            float l2 = lam_of(w2, k0, b2);
            acc_int += (double)(l0 + l1 + l2);
        }
        acc = -(double)RES_D * acc_int;
    }

    // ---- log-sum term: each head's own event times, eq >= 1, mask > 0 ----
    const int QPER = (P_PRED * E_EV) / CHUNKS;   // 192
    if (tid < QPER) {
        int q = chunk * QPER + tid;
        int h = q >> 7, eq = q & 127;
        if (eq >= 1 && sm[h][eq] > 0.0f) {
            float tq = st[h][eq];
            float edk = __expf(__fmul_rn(-DECAY, tq));
            float feat;
            if (h == 0) {
                float k1 = __fmul_rn(edk, pref[1][cut_count(st[1], tq)]);
                float k2 = __fmul_rn(edk, pref[2][cut_count(st[2], tq)]);
                feat = __fadd_rn(k1, k2);
            } else {
                feat = __fmul_rn(edk, pref[0][cut_count(st[0], tq)]);
            }
            float bh = (h == 0) ? b0 : (h == 1) ? b1 : b2;
            float wh = (h == 0) ? w0 : (h == 1) ? w1 : w2;
            acc += (double)logf(lam_of(wh, feat, bh));
        }
    }

    // ---- deterministic block reduce ----
    red[tid] = acc;
    __syncthreads();
#pragma unroll
    for (int off = TPB / 2; off > 0; off >>= 1) {
        if (tid < off) red[tid] += red[tid + off];
        __syncthreads();
    }
    if (tid == 0) {
        g_partials[blockIdx.x] = red[0];
        __threadfence();
        int old = atomicAdd(&g_counter, 1);
        islast = (old == NB - 1) ? 1 : 0;
    }
    __syncthreads();

    // ---- last block: fixed-order deterministic final reduce ----
    if (islast) {
        __threadfence();
        const int PERT = (NB + TPB - 1) / TPB;
        double a = 0.0;
        int b0i = tid * PERT;
        for (int i = 0; i < PERT; ++i) {
            int idx = b0i + i;
            if (idx < NB) a += g_partials[idx];
        }
        red[tid] = a;
        __syncthreads();
#pragma unroll
        for (int off = TPB / 2; off > 0; off >>= 1) {
            if (tid < off) red[tid] += red[tid + off];
            __syncthreads();
        }
        if (tid == 0) {
            out[0] = (float)red[0];
            g_counter = 0;   // reset for next graph replay
        }
    }
}

extern "C" void kernel_launch(void* const* d_in, const int* in_sizes, int n_in,
                              void* d_out, int out_size) {
    const float* event_times = (const float*)d_in[0];
    const float* event_mask  = (const float*)d_in[1];
    const float* base        = (const float*)d_in[2];
    const float* weight      = (const float*)d_in[3];
    const void*  tmax        = d_in[4];

    int S = in_sizes[0] / (P_PRED * E_EV);
    int nblocks = S * CHUNKS;

    hawkes_fused<<<nblocks, TPB>>>(event_times, event_mask, base, weight, tmax,
                                   (float*)d_out);
}

// round 9
// speedup vs baseline: 1.9329x; 1.3469x over previous
#include <cuda_runtime.h>
#include <math.h>
#include <float.h>

// Problem constants (fixed by the dataset)
#define P_PRED 3
#define E_EV   128
#define CHUNKS 2
#define TPB    256
#define NWARP  (TPB / 32)

#define TIME_TOL 0.1f
#define DECAY    0.8f
#define RES_D    0.03

// Scratch (no device allocation allowed anywhere).
__device__ double g_partials[2048];
__device__ int    g_counter = 0;

__device__ __forceinline__ float final_intensity(float raw, float base) {
    return (raw >= 0.0f) ? fmaxf(raw, base) : __expf(raw);
}

__device__ __forceinline__ float lam_of(float w, float feat, float b) {
    float raw = __fadd_rn(b, __fmul_rn(w, feat));   // mirror ref: mul then add
    return final_intensity(raw, b);
}

// Branchless count of events with (t - st[e]) > 0.1f on sorted st[0..128).
// Bit-exact vs the reference's f32 predicate (monotone in te).
__device__ __forceinline__ int cut_count(const float* __restrict__ st, float t) {
    int c = 0;
#pragma unroll
    for (int step = 64; step >= 1; step >>= 1)
        if ((t - st[c + step - 1]) > TIME_TOL) c += step;
    if ((t - st[c]) > TIME_TOL) ++c;    // handles c == 128 exactly
    return c;
}

__device__ __forceinline__ double warp_reduce_f64(double v) {
#pragma unroll
    for (int o = 16; o >= 1; o >>= 1)
        v += __shfl_down_sync(0xffffffffu, v, o);
    return v;
}

__global__ __launch_bounds__(TPB)
void hawkes_fused(const float* __restrict__ event_times,
                  const float* __restrict__ event_mask,
                  const float* __restrict__ base,
                  const float* __restrict__ weight,
                  const void*  __restrict__ tmax_ptr,
                  float* __restrict__ out) {
    const int s     = blockIdx.x / CHUNKS;
    const int chunk = blockIdx.x % CHUNKS;
    const int tid   = threadIdx.x;
    const int NB    = gridDim.x;
    const int wid   = tid >> 5, lane = tid & 31;

    __shared__ float st[P_PRED][E_EV + 1];    // sorted times + FLT_MAX sentinel
    __shared__ float sm[P_PRED][E_EV];        // masks
    __shared__ float pref[P_PRED][E_EV + 1];  // f32 prefix of m*exp(0.8*te)
    __shared__ float sb[P_PRED], sw[P_PRED];
    __shared__ double wred[NWARP];
    __shared__ int islast;

    const float* et = event_times + (size_t)s * P_PRED * E_EV;
    const float* em = event_mask  + (size_t)s * P_PRED * E_EV;

    // ---- fused load + f32 warp-scan: warp w owns predicate w entirely ----
    if (wid < P_PRED) {
        // Issue all 8 loads up-front (MLP = 8).
        float tv[4], mv[4];
#pragma unroll
        for (int seg = 0; seg < 4; ++seg) {
            int e = seg * 32 + lane;
            tv[seg] = et[wid * E_EV + e];
            mv[seg] = em[wid * E_EV + e];
        }
        float carry = 0.0f;
#pragma unroll
        for (int seg = 0; seg < 4; ++seg) {
            int e = seg * 32 + lane;
            st[wid][e] = tv[seg];
            sm[wid][e] = mv[seg];
            float v = __fmul_rn(mv[seg], __expf(__fmul_rn(DECAY, tv[seg])));
#pragma unroll
            for (int o = 1; o < 32; o <<= 1) {
                float n = __shfl_up_sync(0xffffffffu, v, o);
                if (lane >= o) v = __fadd_rn(v, n);
            }
            v = __fadd_rn(v, carry);
            pref[wid][e + 1] = v;
            carry = __shfl_sync(0xffffffffu, v, 31);
        }
        if (lane == 0) {
            pref[wid][0] = 0.0f;
            st[wid][E_EV] = FLT_MAX;          // advance-loop sentinel
        }
    } else if (wid == 3 && lane < P_PRED) {
        sb[lane] = base[lane];
        sw[lane] = weight[lane];
    }
    __syncthreads();

    // Grid count G = ceil(T_max / 0.03); T_max may arrive as int or f32.
    int tmax_i = *(const int*)tmax_ptr;
    if (!(tmax_i > 0 && tmax_i < 1000000)) tmax_i = (int)(*(const float*)tmax_ptr);
    const int G = (int)ceil((double)tmax_i / RES_D);

    const float b0 = sb[0], b1 = sb[1], b2 = sb[2];
    const float w0 = sw[0], w1 = sw[1], w2 = sw[2];

    // ---- integral term: contiguous per-thread range + incremental advance ----
    const int per = (G + CHUNKS - 1) / CHUNKS;
    const int gs  = chunk * per;
    const int ge  = min(gs + per, G);
    const int npt = (per + TPB - 1) / TPB;
    const int r0  = gs + tid * npt;
    const int r1  = min(r0 + npt, ge);

    float acc_int = 0.0f;     // <= ~7 small terms: f32 is plenty
    if (r0 < r1) {
        // One bit-exact binary search for the first point (3 interleaved chains).
        float t0 = (float)((double)r0 * RES_D);
        int c0 = 0, c1 = 0, c2 = 0;
#pragma unroll
        for (int step = 64; step >= 1; step >>= 1) {
            if ((t0 - st[0][c0 + step - 1]) > TIME_TOL) c0 += step;
            if ((t0 - st[1][c1 + step - 1]) > TIME_TOL) c1 += step;
            if ((t0 - st[2][c2 + step - 1]) > TIME_TOL) c2 += step;
        }
        if ((t0 - st[0][c0]) > TIME_TOL) ++c0;
        if ((t0 - st[1][c1]) > TIME_TOL) ++c1;
        if ((t0 - st[2][c2]) > TIME_TOL) ++c2;

        for (int g = r0; g < r1; ++g) {
            float t = (float)((double)g * RES_D);   // matches np.arange(f64) -> f32
            // Monotone incremental advance with the identical predicate.
            while ((t - st[0][c0]) > TIME_TOL) ++c0;
            while ((t - st[1][c1]) > TIME_TOL) ++c1;
            while ((t - st[2][c2]) > TIME_TOL) ++c2;

            float edk = __expf(__fmul_rn(-DECAY, t));
            float k0 = __fmul_rn(edk, pref[0][c0]);
            float k1 = __fmul_rn(edk, pref[1][c1]);
            float k2 = __fmul_rn(edk, pref[2][c2]);

            // BODY = [[0,1,1],[1,0,0],[1,0,0]]
            float l0 = lam_of(w0, __fadd_rn(k1, k2), b0);
            float l1 = lam_of(w1, k0, b1);
            float l2 = lam_of(w2, k0, b2);
            acc_int += (l0 + l1 + l2);
        }
    }

    double acc = -(double)RES_D * (double)acc_int;

    // ---- log-sum term: each head's own event times, eq >= 1, mask > 0 ----
    const int QPER = (P_PRED * E_EV) / CHUNKS;   // 192
    if (tid < QPER) {
        int q = chunk * QPER + tid;
        int h = q >> 7, eq = q & 127;
        if (eq >= 1 && sm[h][eq] > 0.0f) {
            float tq = st[h][eq];
            float edk = __expf(__fmul_rn(-DECAY, tq));
            float feat;
            if (h == 0) {
                float k1 = __fmul_rn(edk, pref[1][cut_count(st[1], tq)]);
                float k2 = __fmul_rn(edk, pref[2][cut_count(st[2], tq)]);
                feat = __fadd_rn(k1, k2);
            } else {
                feat = __fmul_rn(edk, pref[0][cut_count(st[0], tq)]);
            }
            float bh = (h == 0) ? b0 : (h == 1) ? b1 : b2;
            float wh = (h == 0) ? w0 : (h == 1) ? w1 : w2;
            acc += (double)logf(lam_of(wh, feat, bh));
        }
    }

    // ---- deterministic shuffle-based block reduce ----
    double v = warp_reduce_f64(acc);
    if (lane == 0) wred[wid] = v;
    __syncthreads();
    if (wid == 0) {
        double a = (lane < NWARP) ? wred[lane] : 0.0;
#pragma unroll
        for (int o = 4; o >= 1; o >>= 1)
            a += __shfl_down_sync(0xffffffffu, a, o);
        if (lane == 0) {
            g_partials[blockIdx.x] = a;
            __threadfence();
            int old = atomicAdd(&g_counter, 1);
            islast = (old == NB - 1) ? 1 : 0;
        }
    }
    __syncthreads();

    // ---- last block: fixed-order deterministic final reduce ----
    if (islast) {
        __threadfence();
        double a = (tid < NB) ? g_partials[tid] : 0.0;
        a = warp_reduce_f64(a);
        if (lane == 0) wred[wid] = a;
        __syncthreads();
        if (wid == 0) {
            double b = (lane < NWARP) ? wred[lane] : 0.0;
#pragma unroll
            for (int o = 4; o >= 1; o >>= 1)
                b += __shfl_down_sync(0xffffffffu, b, o);
            if (lane == 0) {
                out[0] = (float)b;
                g_counter = 0;   // reset for next graph replay
            }
        }
    }
}

extern "C" void kernel_launch(void* const* d_in, const int* in_sizes, int n_in,
                              void* d_out, int out_size) {
    const float* event_times = (const float*)d_in[0];
    const float* event_mask  = (const float*)d_in[1];
    const float* base        = (const float*)d_in[2];
    const float* weight      = (const float*)d_in[3];
    const void*  tmax        = d_in[4];

    int S = in_sizes[0] / (P_PRED * E_EV);
    int nblocks = S * CHUNKS;

    hawkes_fused<<<nblocks, TPB>>>(event_times, event_mask, base, weight, tmax,
                                   (float*)d_out);
}